// round 7
// baseline (speedup 1.0000x reference)
#include <cuda_runtime.h>
#include <math.h>

#define TT  50
#define BB  1024
#define BEL 200
#define ST  30
#define ACT 8
#define EMB 1024

static const size_t OFF_B  = 0;
static const size_t OFF_PS = (size_t)TT * BB * BEL;
static const size_t SZ30   = (size_t)TT * BB * ST;
static const size_t OFF_MP = OFF_PS + SZ30;
static const size_t OFF_SP = OFF_MP + SZ30;
static const size_t OFF_PO = OFF_SP + SZ30;
static const size_t OFF_MQ = OFF_PO + SZ30;
static const size_t OFF_SQ = OFF_MQ + SZ30;

__device__ __align__(16) float g_obs[(size_t)TT * BB * BEL];
__device__ __align__(16) float g_Wsa[8000];     // [k4][j(200)][4k], K padded 38->40
__device__ __align__(16) float g_Wg4[240000];   // [k4][cg(300)][4c][4k] cg<150: W_ih else W_hh
__device__ __align__(16) float g_Wh4[80000];    // [k4][cg(100)][4c][4k] col<200: W_bp else W_bq_b
__device__ __align__(16) float g_Wo4[24000];    // [k4][cg(30)][4c][4k]  col<60: W_sp else W_sq

typedef unsigned long long u64;

__device__ __forceinline__ void ffma2(u64& acc, u64 a, u64 b) {
    asm("fma.rn.f32x2 %0, %1, %2, %0;" : "+l"(acc) : "l"(a), "l"(b));
}
__device__ __forceinline__ float hsum2(u64 v) {
    float lo, hi;
    asm("mov.b64 {%0,%1}, %2;" : "=f"(lo), "=f"(hi) : "l"(v));
    return lo + hi;
}
__device__ __forceinline__ float sigm(float x) { return 1.f / (1.f + __expf(-x)); }
__device__ __forceinline__ float tanhfast(float x) { return 1.f - 2.f / (__expf(2.f * x) + 1.f); }
__device__ __forceinline__ float softplusf(float x) {
    return fmaxf(x, 0.f) + log1pf(__expf(-fabsf(x)));
}

// ---------------------------------------------------------------------------
#define PREP_N 352000
__global__ void k_prep(const float* __restrict__ W_sa, const float* __restrict__ W_ih,
                       const float* __restrict__ W_hh, const float* __restrict__ W_bp,
                       const float* __restrict__ W_sp, const float* __restrict__ W_bq,
                       const float* __restrict__ W_sq) {
    int idx = blockIdx.x * blockDim.x + threadIdx.x;
    if (idx >= PREP_N) return;
    if (idx < 8000) {
        int k4 = idx / 800, r = idx % 800, j = r >> 2, k = 4 * k4 + (r & 3);
        g_Wsa[idx] = (k < 38) ? W_sa[j * 38 + k] : 0.f;
        return;
    }
    if (idx < 248000) {
        int l = idx - 8000, k4 = l / 4800, r = l % 4800;
        int cg = r >> 4, c = (r >> 2) & 3, k = 4 * k4 + (r & 3);
        g_Wg4[l] = (cg < 150) ? W_ih[(4 * cg + c) * 200 + k]
                              : W_hh[(4 * (cg - 150) + c) * 200 + k];
        return;
    }
    if (idx < 328000) {
        int l = idx - 248000, k4 = l / 1600, r = l % 1600;
        int cg = r >> 4, c = (r >> 2) & 3, k = 4 * k4 + (r & 3);
        int col = 4 * cg + c;
        g_Wh4[l] = (col < 200) ? W_bp[col * 200 + k]
                               : W_bq[(size_t)(col - 200) * 1224 + k];
        return;
    }
    {
        int l = idx - 328000, k4 = l / 480, r = l % 480;
        int cg = r >> 4, c = (r >> 2) & 3, k = 4 * k4 + (r & 3);
        int col = 4 * cg + c;
        g_Wo4[l] = (col < 60) ? W_sp[col * 200 + k] : W_sq[(col - 60) * 200 + k];
    }
}

// ---------------------------------------------------------------------------
// Obs GEMM: 640 threads (5 warps/SMSP), tile 2x10, double-buffered.
// ---------------------------------------------------------------------------
__global__ __launch_bounds__(640, 1) void k_obs_gemm(const float* __restrict__ A,
                                                     const float* __restrict__ W_bq,
                                                     const float* __restrict__ b_bq) {
    __shared__ __align__(16) float As[2][64 * 20];
    __shared__ __align__(16) float Bs[2][200 * 18];
    const int tid = threadIdx.x;
    const size_t row0 = (size_t)blockIdx.x * 64;
    const int r0 = (tid / 20) * 2, c0 = (tid % 20) * 10;
    u64 acc[2][10];
#pragma unroll
    for (int i = 0; i < 2; i++)
#pragma unroll
        for (int j = 0; j < 10; j++) acc[i][j] = 0ULL;
    const int arow = tid >> 2, ak4 = tid & 3;
    if (tid < 256)
        *(float4*)&As[0][arow * 20 + ak4 * 4] = *(const float4*)&A[(row0 + arow) * EMB + ak4 * 4];
    for (int idx = tid; idx < 800; idx += 640) {
        int col = idx >> 2, e4 = idx & 3;
        float4 v = *(const float4*)&W_bq[(size_t)col * 1224 + 200 + e4 * 4];
        Bs[0][col * 18 + e4 * 4 + 0] = v.x; Bs[0][col * 18 + e4 * 4 + 1] = v.y;
        Bs[0][col * 18 + e4 * 4 + 2] = v.z; Bs[0][col * 18 + e4 * 4 + 3] = v.w;
    }
    __syncthreads();
    for (int kti = 0; kti < 64; kti++) {
        const int cur = kti & 1;
        const bool hn = (kti + 1) < 64;
        float4 pa; float4 pb[2]; int nb = 0;
        if (hn) {
            int kt = (kti + 1) * 16;
            if (tid < 256) pa = *(const float4*)&A[(row0 + arow) * EMB + kt + ak4 * 4];
            for (int idx = tid; idx < 800; idx += 640) {
                int col = idx >> 2, e4 = idx & 3;
                pb[nb++] = *(const float4*)&W_bq[(size_t)col * 1224 + 200 + kt + e4 * 4];
            }
        }
#pragma unroll
        for (int kp = 0; kp < 8; kp++) {
            u64 a2[2], b2[10];
#pragma unroll
            for (int i = 0; i < 2; i++) a2[i] = *(const u64*)&As[cur][(r0 + i) * 20 + 2 * kp];
#pragma unroll
            for (int j = 0; j < 10; j++) b2[j] = *(const u64*)&Bs[cur][(c0 + j) * 18 + 2 * kp];
#pragma unroll
            for (int i = 0; i < 2; i++)
#pragma unroll
                for (int j = 0; j < 10; j++) ffma2(acc[i][j], a2[i], b2[j]);
        }
        if (hn) {
            int nxt = cur ^ 1;
            if (tid < 256) *(float4*)&As[nxt][arow * 20 + ak4 * 4] = pa;
            nb = 0;
            for (int idx = tid; idx < 800; idx += 640) {
                int col = idx >> 2, e4 = idx & 3;
                float4 v = pb[nb++];
                Bs[nxt][col * 18 + e4 * 4 + 0] = v.x; Bs[nxt][col * 18 + e4 * 4 + 1] = v.y;
                Bs[nxt][col * 18 + e4 * 4 + 2] = v.z; Bs[nxt][col * 18 + e4 * 4 + 3] = v.w;
            }
        }
        __syncthreads();
    }
#pragma unroll
    for (int i = 0; i < 2; i++)
#pragma unroll
        for (int j = 0; j < 10; j++)
            g_obs[(row0 + r0 + i) * BEL + c0 + j] = hsum2(acc[i][j]) + b_bq[c0 + j];
}

// ---------------------------------------------------------------------------
// Persistent scan: 128 blocks x 640 threads, 8 rows/block.
// All GEMM phases: 600 threads, C=4 cols x R=4 rows register tiles (32 acc regs).
// ---------------------------------------------------------------------------
#define SCAN_SMEM (29040 * 4)

__global__ __launch_bounds__(640, 1) void k_scan(
    const float* __restrict__ nonterm, const float* __restrict__ prev_state,
    const float* __restrict__ prev_belief, const float* __restrict__ actions,
    const float* __restrict__ noise_p, const float* __restrict__ noise_q,
    const float* __restrict__ b_sa, const float* __restrict__ b_ih,
    const float* __restrict__ b_hh, const float* __restrict__ b_bp,
    const float* __restrict__ b_sp, const float* __restrict__ b_sq,
    float* __restrict__ out) {
    extern __shared__ __align__(16) float sm[];
    float* s_sh  = sm;             // 320  (8 rows x 40)
    float* hid   = sm + 320;       // 1600
    float* bel   = hid + 1600;     // 1600
    float* scr   = bel + 1600;     // 19200 (PhB gates 9600 / PhD part 9600 / PhE part 9600)
    float* obs   = scr + 19200;    // 1600
    float* hp    = obs + 1600;     // 1600
    float* hq    = hp + 1600;      // 1600
    float* bias  = hq + 1600;      // 120
    float* bbp   = bias + 120;     // 200
    float* gbias = bbp + 200;      // 1200 (b_ih | b_hh)

    const int tid = threadIdx.x;
    const int b0 = blockIdx.x * 8;

    float r_bsa = 0.f;
    if (tid < 200) r_bsa = b_sa[tid];
    if (tid < 600) { gbias[tid] = b_ih[tid]; gbias[600 + tid] = b_hh[tid]; }
    if (tid < 120) bias[tid] = (tid < 60) ? b_sp[tid] : b_sq[tid - 60];
    if (tid < 200) bbp[tid] = b_bp[tid];

    for (int idx = tid; idx < 1600; idx += 640) {
        int bb = idx / 200, j = idx % 200;
        bel[idx] = prev_belief[(size_t)(b0 + bb) * BEL + j];
    }
    if (tid < 320) {
        int bb = tid / 40, c = tid % 40;
        float v = 0.f;
        if (c < 30)      v = prev_state[(size_t)(b0 + bb) * ST + c] * nonterm[b0 + bb];
        else if (c < 38) v = actions[(size_t)(b0 + bb) * ACT + (c - 30)];
        s_sh[tid] = v;
    }
    __syncthreads();

    for (int t = 0; t < TT; t++) {
        // ===== PhA: hidden = relu(s_a @ Wsa^T + b_sa) | obs staging =====
        if (tid < 200) {
            u64 acc[8];
#pragma unroll
            for (int r = 0; r < 8; r++) acc[r] = 0ULL;
#pragma unroll
            for (int k4 = 0; k4 < 10; k4++) {
                ulonglong2 w = __ldg((const ulonglong2*)&g_Wsa[(k4 * 200 + tid) * 4]);
#pragma unroll
                for (int r = 0; r < 8; r++) {
                    ulonglong2 s = *(const ulonglong2*)&s_sh[r * 40 + k4 * 4];
                    ffma2(acc[r], s.x, w.x);
                    ffma2(acc[r], s.y, w.y);
                }
            }
#pragma unroll
            for (int r = 0; r < 8; r++)
                hid[r * 200 + tid] = fmaxf(hsum2(acc[r]) + r_bsa, 0.f);
        } else if (tid < 600) {
            int i = tid - 200;
            *(float4*)&obs[i * 4] = *(const float4*)&g_obs[((size_t)t * BB + b0) * BEL + i * 4];
        }
        __syncthreads();

        // ===== PhB: 1200 gate cols = 300 cg x (C4 x R4) x 2 rowhalves =====
        if (tid < 600) {
            const int cg = tid >> 1, rb = (tid & 1) * 4;
            const float* src = (cg < 150) ? hid : bel;
            const ulonglong2* wp = (const ulonglong2*)g_Wg4 + cg * 4;
            u64 acc[4][4];
#pragma unroll
            for (int c = 0; c < 4; c++)
#pragma unroll
                for (int r = 0; r < 4; r++) acc[c][r] = 0ULL;
            ulonglong2 wn[4];
#pragma unroll
            for (int c = 0; c < 4; c++) wn[c] = wp[c];
            for (int k4 = 0; k4 < 50; k4++) {
                ulonglong2 wc[4];
#pragma unroll
                for (int c = 0; c < 4; c++) wc[c] = wn[c];
                if (k4 + 1 < 50) {
#pragma unroll
                    for (int c = 0; c < 4; c++) wn[c] = wp[(k4 + 1) * 1200 + c];
                }
#pragma unroll
                for (int rr = 0; rr < 4; rr++) {
                    ulonglong2 h = *(const ulonglong2*)&src[(rb + rr) * 200 + k4 * 4];
#pragma unroll
                    for (int c = 0; c < 4; c++) {
                        ffma2(acc[c][rr], h.x, wc[c].x);
                        ffma2(acc[c][rr], h.y, wc[c].y);
                    }
                }
            }
#pragma unroll
            for (int rr = 0; rr < 4; rr++) {
                float4 v = make_float4(hsum2(acc[0][rr]), hsum2(acc[1][rr]),
                                       hsum2(acc[2][rr]), hsum2(acc[3][rr]));
                *(float4*)&scr[(rb + rr) * 1200 + 4 * cg] = v;
            }
        }
        __syncthreads();

        // ===== PhC: GRU combine (400 threads x 4 rows) =====
        if (tid < 400) {
            const int j = tid % 200, rb = (tid / 200) * 4;
            float bir = gbias[j], biz = gbias[200 + j], bin = gbias[400 + j];
            float bhr = gbias[600 + j], bhz = gbias[800 + j], bhn = gbias[1000 + j];
#pragma unroll
            for (int rr = 0; rr < 4; rr++) {
                const int r = rb + rr;
                const float* g = &scr[r * 1200];
                float rg = sigm(g[j] + bir + g[600 + j] + bhr);
                float z  = sigm(g[200 + j] + biz + g[800 + j] + bhz);
                float n  = tanhfast(g[400 + j] + bin + rg * (g[1000 + j] + bhn));
                float nb = (1.f - z) * n + z * bel[r * 200 + j];
                bel[r * 200 + j] = nb;
                out[OFF_B + ((size_t)t * BB + b0 + r) * BEL + j] = nb;
            }
        }
        __syncthreads();

        // ===== PhD: hp/hq pre-acts: 100 cg x 2 rowhalves x 3 ksplits =====
        if (tid < 600) {
            const int q = tid / 200, r2 = tid % 200, cg = r2 >> 1, rb = (r2 & 1) * 4;
            const int kbeg = q * 17, kend = (q < 2) ? kbeg + 17 : 50;
            const ulonglong2* wp = (const ulonglong2*)g_Wh4 + cg * 4;
            u64 acc[4][4];
#pragma unroll
            for (int c = 0; c < 4; c++)
#pragma unroll
                for (int r = 0; r < 4; r++) acc[c][r] = 0ULL;
            ulonglong2 wn[4];
#pragma unroll
            for (int c = 0; c < 4; c++) wn[c] = wp[kbeg * 400 + c];
            for (int k4 = kbeg; k4 < kend; k4++) {
                ulonglong2 wc[4];
#pragma unroll
                for (int c = 0; c < 4; c++) wc[c] = wn[c];
                if (k4 + 1 < kend) {
#pragma unroll
                    for (int c = 0; c < 4; c++) wn[c] = wp[(k4 + 1) * 400 + c];
                }
#pragma unroll
                for (int rr = 0; rr < 4; rr++) {
                    ulonglong2 h = *(const ulonglong2*)&bel[(rb + rr) * 200 + k4 * 4];
#pragma unroll
                    for (int c = 0; c < 4; c++) {
                        ffma2(acc[c][rr], h.x, wc[c].x);
                        ffma2(acc[c][rr], h.y, wc[c].y);
                    }
                }
            }
#pragma unroll
            for (int rr = 0; rr < 4; rr++) {
                float4 v = make_float4(hsum2(acc[0][rr]), hsum2(acc[1][rr]),
                                       hsum2(acc[2][rr]), hsum2(acc[3][rr]));
                *(float4*)&scr[q * 3200 + (rb + rr) * 400 + 4 * cg] = v;
            }
        }
        __syncthreads();

        // ===== reduce 3 partials -> hp/hq (+bias/obs, relu); 640x5 =====
#pragma unroll
        for (int k = 0; k < 5; k++) {
            int id = tid + k * 640;
            int col = id % 400, r = id / 400;
            float v = scr[r * 400 + col] + scr[3200 + r * 400 + col] +
                      scr[6400 + r * 400 + col];
            if (col < 200) hp[r * 200 + col] = fmaxf(v + bbp[col], 0.f);
            else hq[r * 200 + col - 200] = fmaxf(v + obs[r * 200 + col - 200], 0.f);
        }
        __syncthreads();

        // ===== PhE: heads: 30 cg x 2 rowhalves x 10 ksplits =====
        if (tid < 600) {
            const int q = tid / 60, r2 = tid % 60, cg = r2 >> 1, rb = (r2 & 1) * 4;
            const float* src = (cg < 15) ? hp : hq;
            u64 acc[4][4];
#pragma unroll
            for (int c = 0; c < 4; c++)
#pragma unroll
                for (int r = 0; r < 4; r++) acc[c][r] = 0ULL;
#pragma unroll
            for (int kk = 0; kk < 5; kk++) {
                int k4 = q * 5 + kk;
                ulonglong2 wc[4];
#pragma unroll
                for (int c = 0; c < 4; c++)
                    wc[c] = __ldg((const ulonglong2*)g_Wo4 + k4 * 120 + cg * 4 + c);
#pragma unroll
                for (int rr = 0; rr < 4; rr++) {
                    ulonglong2 h = *(const ulonglong2*)&src[(rb + rr) * 200 + k4 * 4];
#pragma unroll
                    for (int c = 0; c < 4; c++) {
                        ffma2(acc[c][rr], h.x, wc[c].x);
                        ffma2(acc[c][rr], h.y, wc[c].y);
                    }
                }
            }
#pragma unroll
            for (int rr = 0; rr < 4; rr++) {
                float4 v = make_float4(hsum2(acc[0][rr]), hsum2(acc[1][rr]),
                                       hsum2(acc[2][rr]), hsum2(acc[3][rr]));
                *(float4*)&scr[q * 960 + (rb + rr) * 120 + 4 * cg] = v;
            }
        }
        __syncthreads();

        // ===== PhF: reduce 10 partials, sample, write, next s_sh =====
        if (tid < 240) {
            const int bb = tid / 30, i = tid - bb * 30;
            size_t gidx = ((size_t)t * BB + b0 + bb) * ST + i;
            float np = noise_p[gidx], nq = noise_q[gidx];
            float mp = bias[i], spr = bias[30 + i], mq = bias[60 + i], sqr = bias[90 + i];
#pragma unroll
            for (int q = 0; q < 10; q++) {
                const float* p = &scr[q * 960 + bb * 120];
                mp += p[i]; spr += p[30 + i]; mq += p[60 + i]; sqr += p[90 + i];
            }
            float spv = softplusf(spr) + 0.1f;
            float sqv = softplusf(sqr) + 0.1f;
            float po  = fmaf(sqv, nq, mq);
            out[OFF_MP + gidx] = mp;
            out[OFF_SP + gidx] = spv;
            out[OFF_PS + gidx] = fmaf(spv, np, mp);
            out[OFF_MQ + gidx] = mq;
            out[OFF_SQ + gidx] = sqv;
            out[OFF_PO + gidx] = po;
            if (t + 1 < TT)
                s_sh[bb * 40 + i] = po * nonterm[(size_t)(t + 1) * BB + b0 + bb];
        } else if (tid < 304) {
            int idx = tid - 240, bb = idx >> 3, i = idx & 7;
            if (t + 1 < TT)
                s_sh[bb * 40 + 30 + i] = actions[((size_t)(t + 1) * BB + b0 + bb) * ACT + i];
        }
        __syncthreads();
    }
}

// ---------------------------------------------------------------------------
extern "C" void kernel_launch(void* const* d_in, const int* in_sizes, int n_in,
                              void* d_out, int out_size) {
    const float* prev_state   = (const float*)d_in[0];
    const float* actions      = (const float*)d_in[1];
    const float* prev_belief  = (const float*)d_in[2];
    const float* observations = (const float*)d_in[3];
    const float* nonterm      = (const float*)d_in[4];
    const float* noise_p      = (const float*)d_in[5];
    const float* noise_q      = (const float*)d_in[6];
    const float* W_sa = (const float*)d_in[7];  const float* b_sa = (const float*)d_in[8];
    const float* W_ih = (const float*)d_in[9];  const float* b_ih = (const float*)d_in[10];
    const float* W_hh = (const float*)d_in[11]; const float* b_hh = (const float*)d_in[12];
    const float* W_bp = (const float*)d_in[13]; const float* b_bp = (const float*)d_in[14];
    const float* W_sp = (const float*)d_in[15]; const float* b_sp = (const float*)d_in[16];
    const float* W_bq = (const float*)d_in[17]; const float* b_bq = (const float*)d_in[18];
    const float* W_sq = (const float*)d_in[19]; const float* b_sq = (const float*)d_in[20];
    float* out = (float*)d_out;
    (void)in_sizes; (void)n_in; (void)out_size;

    static int done = 0;
    if (!done) {
        cudaFuncSetAttribute(k_scan, cudaFuncAttributeMaxDynamicSharedMemorySize, SCAN_SMEM);
        done = 1;
    }
    k_prep<<<(PREP_N + 255) / 256, 256>>>(W_sa, W_ih, W_hh, W_bp, W_sp, W_bq, W_sq);
    k_obs_gemm<<<(TT * BB) / 64, 640>>>(observations, W_bq, b_bq);
    k_scan<<<BB / 8, 640, SCAN_SMEM>>>(nonterm, prev_state, prev_belief, actions,
                                       noise_p, noise_q, b_sa, b_ih, b_hh,
                                       b_bp, b_sp, b_sq, out);
}

// round 8
// speedup vs baseline: 1.0962x; 1.0962x over previous
#include <cuda_runtime.h>
#include <math.h>

#define TT  50
#define BB  1024
#define BEL 200
#define ST  30
#define ACT 8
#define EMB 1024

static const size_t OFF_B  = 0;
static const size_t OFF_PS = (size_t)TT * BB * BEL;
static const size_t SZ30   = (size_t)TT * BB * ST;
static const size_t OFF_MP = OFF_PS + SZ30;
static const size_t OFF_SP = OFF_MP + SZ30;
static const size_t OFF_PO = OFF_SP + SZ30;
static const size_t OFF_MQ = OFF_PO + SZ30;
static const size_t OFF_SQ = OFF_MQ + SZ30;

__device__ __align__(16) float g_obs[(size_t)TT * BB * BEL];
// R3-proven layouts:
__device__ __align__(16) float g_Wg2[240000];  // [k4][tc(600)][2cols][4k]; tc<300: W_ih else W_hh
__device__ __align__(16) float g_Wsa[8000];    // [k4(10)][j(200)][4k], K padded 38->40 (state+action)
__device__ __align__(16) float g_Wh2[80000];   // [k4][p(200)][2cols][4k]; p<100: W_bp else W_bq_b
__device__ __align__(16) float g_Wo4[24000];   // [k4][g(120)][4k]; g<60: W_sp else W_sq

typedef unsigned long long u64;

__device__ __forceinline__ void ffma2(u64& acc, u64 a, u64 b) {
    asm("fma.rn.f32x2 %0, %1, %2, %0;" : "+l"(acc) : "l"(a), "l"(b));
}
__device__ __forceinline__ float hsum2(u64 v) {
    float lo, hi;
    asm("mov.b64 {%0,%1}, %2;" : "=f"(lo), "=f"(hi) : "l"(v));
    return lo + hi;
}
__device__ __forceinline__ float sigm(float x) { return 1.f / (1.f + __expf(-x)); }
__device__ __forceinline__ float tanhfast(float x) { return 1.f - 2.f / (__expf(2.f * x) + 1.f); }
__device__ __forceinline__ float softplusf(float x) {
    return fmaxf(x, 0.f) + log1pf(__expf(-fabsf(x)));
}

// ---------------------------------------------------------------------------
#define PREP_N 352000
__global__ void k_prep(const float* __restrict__ W_sa, const float* __restrict__ W_ih,
                       const float* __restrict__ W_hh, const float* __restrict__ W_bp,
                       const float* __restrict__ W_sp, const float* __restrict__ W_bq,
                       const float* __restrict__ W_sq) {
    int idx = blockIdx.x * blockDim.x + threadIdx.x;
    if (idx >= PREP_N) return;
    if (idx < 240000) {  // g_Wg2
        int kk = idx & 3, t1 = idx >> 2;
        int cc = t1 & 1, t2 = t1 >> 1;
        int tc = t2 % 600, k4 = t2 / 600, k = 4 * k4 + kk;
        g_Wg2[idx] = (tc < 300) ? W_ih[(2 * tc + cc) * 200 + k]
                                : W_hh[(2 * (tc - 300) + cc) * 200 + k];
        return;
    }
    idx -= 240000;
    if (idx < 8000) {    // g_Wsa (state+action, K padded to 40)
        int kk = idx & 3, t = idx >> 2;
        int j = t % 200, k4 = t / 200, k = 4 * k4 + kk;
        g_Wsa[idx] = (k < 38) ? W_sa[j * 38 + k] : 0.f;
        return;
    }
    idx -= 8000;
    if (idx < 80000) {   // g_Wh2
        int kk = idx & 3, t1 = idx >> 2;
        int cc = t1 & 1, t2 = t1 >> 1;
        int p = t2 % 200, k4 = t2 / 200, k = 4 * k4 + kk;
        g_Wh2[idx] = (p < 100) ? W_bp[(2 * p + cc) * 200 + k]
                               : W_bq[(size_t)(2 * (p - 100) + cc) * 1224 + k];
        return;
    }
    idx -= 80000;
    {                    // g_Wo4
        int kk = idx & 3, t = idx >> 2;
        int g = t % 120, k4 = t / 120, k = 4 * k4 + kk;
        g_Wo4[idx] = (g < 60) ? W_sp[g * 200 + k] : W_sq[(g - 60) * 200 + k];
    }
}

// ---------------------------------------------------------------------------
// Obs GEMM: 640 threads (5 warps/SMSP), tile 2x10, double-buffered.
// ---------------------------------------------------------------------------
__global__ __launch_bounds__(640, 1) void k_obs_gemm(const float* __restrict__ A,
                                                     const float* __restrict__ W_bq,
                                                     const float* __restrict__ b_bq) {
    __shared__ __align__(16) float As[2][64 * 20];
    __shared__ __align__(16) float Bs[2][200 * 18];
    const int tid = threadIdx.x;
    const size_t row0 = (size_t)blockIdx.x * 64;
    const int r0 = (tid / 20) * 2, c0 = (tid % 20) * 10;
    u64 acc[2][10];
#pragma unroll
    for (int i = 0; i < 2; i++)
#pragma unroll
        for (int j = 0; j < 10; j++) acc[i][j] = 0ULL;
    const int arow = tid >> 2, ak4 = tid & 3;
    if (tid < 256)
        *(float4*)&As[0][arow * 20 + ak4 * 4] = *(const float4*)&A[(row0 + arow) * EMB + ak4 * 4];
    for (int idx = tid; idx < 800; idx += 640) {
        int col = idx >> 2, e4 = idx & 3;
        float4 v = *(const float4*)&W_bq[(size_t)col * 1224 + 200 + e4 * 4];
        Bs[0][col * 18 + e4 * 4 + 0] = v.x; Bs[0][col * 18 + e4 * 4 + 1] = v.y;
        Bs[0][col * 18 + e4 * 4 + 2] = v.z; Bs[0][col * 18 + e4 * 4 + 3] = v.w;
    }
    __syncthreads();
    for (int kti = 0; kti < 64; kti++) {
        const int cur = kti & 1;
        const bool hn = (kti + 1) < 64;
        float4 pa; float4 pb[2]; int nb = 0;
        if (hn) {
            int kt = (kti + 1) * 16;
            if (tid < 256) pa = *(const float4*)&A[(row0 + arow) * EMB + kt + ak4 * 4];
            for (int idx = tid; idx < 800; idx += 640) {
                int col = idx >> 2, e4 = idx & 3;
                pb[nb++] = *(const float4*)&W_bq[(size_t)col * 1224 + 200 + kt + e4 * 4];
            }
        }
#pragma unroll
        for (int kp = 0; kp < 8; kp++) {
            u64 a2[2], b2[10];
#pragma unroll
            for (int i = 0; i < 2; i++) a2[i] = *(const u64*)&As[cur][(r0 + i) * 20 + 2 * kp];
#pragma unroll
            for (int j = 0; j < 10; j++) b2[j] = *(const u64*)&Bs[cur][(c0 + j) * 18 + 2 * kp];
#pragma unroll
            for (int i = 0; i < 2; i++)
#pragma unroll
                for (int j = 0; j < 10; j++) ffma2(acc[i][j], a2[i], b2[j]);
        }
        if (hn) {
            int nxt = cur ^ 1;
            if (tid < 256) *(float4*)&As[nxt][arow * 20 + ak4 * 4] = pa;
            nb = 0;
            for (int idx = tid; idx < 800; idx += 640) {
                int col = idx >> 2, e4 = idx & 3;
                float4 v = pb[nb++];
                Bs[nxt][col * 18 + e4 * 4 + 0] = v.x; Bs[nxt][col * 18 + e4 * 4 + 1] = v.y;
                Bs[nxt][col * 18 + e4 * 4 + 2] = v.z; Bs[nxt][col * 18 + e4 * 4 + 3] = v.w;
            }
        }
        __syncthreads();
    }
#pragma unroll
    for (int i = 0; i < 2; i++)
#pragma unroll
        for (int j = 0; j < 10; j++)
            g_obs[(row0 + r0 + i) * BEL + c0 + j] = hsum2(acc[i][j]) + b_bq[c0 + j];
}

// ---------------------------------------------------------------------------
// Persistent scan (R3-proven structure): 128 blocks x 640 threads, 8 rows/block.
// PhA now folds the action projection (s_sh is 40 wide; K padded to 40).
// ---------------------------------------------------------------------------
#define SCAN_SMEM (18040 * 4)

__global__ __launch_bounds__(640, 1) void k_scan(
    const float* __restrict__ nonterm, const float* __restrict__ prev_state,
    const float* __restrict__ prev_belief, const float* __restrict__ actions,
    const float* __restrict__ noise_p, const float* __restrict__ noise_q,
    const float* __restrict__ b_sa, const float* __restrict__ b_ih,
    const float* __restrict__ b_hh, const float* __restrict__ b_bp,
    const float* __restrict__ b_sp, const float* __restrict__ b_sq,
    float* __restrict__ out) {
    extern __shared__ float sm[];
    float* s_sh = sm;            // 8x40 = 320
    float* hid  = sm + 320;      // 1600
    float* bel  = hid + 1600;    // 1600
    float* gig  = bel + 1600;    // 9600 (gi@0, gh@4800; reused: PhD partials / PhE partials)
    float* obs  = gig + 9600;    // 1600
    float* hp   = obs + 1600;    // 1600
    float* hq   = hp + 1600;     // 1600
    float* bias = hq + 1600;     // 120   => 18040 floats

    const int tid = threadIdx.x;
    const int b0 = blockIdx.x * 8;

    float r_bsa = 0.f, r_bir = 0.f, r_biz = 0.f, r_bin = 0.f;
    float r_bhr = 0.f, r_bhz = 0.f, r_bhn = 0.f, r_bbp = 0.f;
    if (tid < 200) {
        r_bsa = b_sa[tid];
        r_bir = b_ih[tid]; r_biz = b_ih[200 + tid]; r_bin = b_ih[400 + tid];
        r_bhr = b_hh[tid]; r_bhz = b_hh[200 + tid]; r_bhn = b_hh[400 + tid];
        r_bbp = b_bp[tid];
    }
    if (tid < 120) bias[tid] = (tid < 60) ? b_sp[tid] : b_sq[tid - 60];

    for (int idx = tid; idx < 8 * BEL; idx += 640) {
        int bb = idx / BEL, j = idx - bb * BEL;
        bel[idx] = prev_belief[(size_t)(b0 + bb) * BEL + j];
    }
    if (tid < 320) {
        int bb = tid / 40, c = tid % 40;
        float v = 0.f;
        if (c < 30)      v = prev_state[(size_t)(b0 + bb) * ST + c] * nonterm[b0 + bb];
        else if (c < 38) v = actions[(size_t)(b0 + bb) * ACT + (c - 30)];
        s_sh[tid] = v;
    }
    __syncthreads();

    for (int t = 0; t < TT; t++) {
        // ===== PhA: hidden = relu([s|a] @ Wsa^T + b_sa) | obs staging =====
        if (tid < 200) {
            u64 acc[8];
#pragma unroll
            for (int bb = 0; bb < 8; bb++) acc[bb] = 0ULL;
#pragma unroll
            for (int k4 = 0; k4 < 10; k4++) {
                ulonglong2 w = __ldg((const ulonglong2*)&g_Wsa[(k4 * 200 + tid) << 2]);
#pragma unroll
                for (int bb = 0; bb < 8; bb++) {
                    ulonglong2 s = *(const ulonglong2*)&s_sh[bb * 40 + k4 * 4];
                    ffma2(acc[bb], s.x, w.x);
                    ffma2(acc[bb], s.y, w.y);
                }
            }
#pragma unroll
            for (int bb = 0; bb < 8; bb++)
                hid[bb * 200 + tid] = fmaxf(hsum2(acc[bb]) + r_bsa, 0.f);
        } else if (tid < 600) {
            int i = tid - 200;
            *(float4*)&obs[i * 4] = *(const float4*)&g_obs[((size_t)t * BB + b0) * BEL + i * 4];
        }
        __syncthreads();

        // ===== PhB: gi + gh, 600 threads, 2 cols each, depth-2 prefetch =====
        if (tid < 600) {
            const float* src = (tid < 300) ? hid : bel;
            const ulonglong2* __restrict__ wp = (const ulonglong2*)g_Wg2 + tid * 2;
            u64 accA[8], accB[8];
#pragma unroll
            for (int bb = 0; bb < 8; bb++) { accA[bb] = 0ULL; accB[bb] = 0ULL; }
            ulonglong2 w0a = wp[0],    w0b = wp[1];
            ulonglong2 w1a = wp[1200], w1b = wp[1201];
#pragma unroll 2
            for (int k4 = 0; k4 < 50; k4++) {
                ulonglong2 wa = w0a, wb = w0b;
                w0a = w1a; w0b = w1b;
                if (k4 + 2 < 50) {
                    w1a = wp[(k4 + 2) * 1200];
                    w1b = wp[(k4 + 2) * 1200 + 1];
                }
#pragma unroll
                for (int bb = 0; bb < 8; bb++) {
                    ulonglong2 h = *(const ulonglong2*)&src[bb * 200 + k4 * 4];
                    ffma2(accA[bb], h.x, wa.x); ffma2(accA[bb], h.y, wa.y);
                    ffma2(accB[bb], h.x, wb.x); ffma2(accB[bb], h.y, wb.y);
                }
            }
            int p = (tid < 300) ? tid : tid - 300;
            float* dst = (tid < 300) ? gig : (gig + 4800);
#pragma unroll
            for (int bb = 0; bb < 8; bb++) {
                dst[bb * 600 + 2 * p]     = hsum2(accA[bb]);
                dst[bb * 600 + 2 * p + 1] = hsum2(accB[bb]);
            }
        }
        __syncthreads();

        // ===== PhC: GRU combine -> new belief =====
        if (tid < 200) {
            const int j = tid;
            const float* gh = gig + 4800;
#pragma unroll
            for (int bb = 0; bb < 8; bb++) {
                float r = sigm(gig[bb * 600 + j] + r_bir + gh[bb * 600 + j] + r_bhr);
                float z = sigm(gig[bb * 600 + 200 + j] + r_biz + gh[bb * 600 + 200 + j] + r_bhz);
                float n = tanhfast(gig[bb * 600 + 400 + j] + r_bin +
                                   r * (gh[bb * 600 + 400 + j] + r_bhn));
                float nb = (1.f - z) * n + z * bel[bb * 200 + j];
                bel[bb * 200 + j] = nb;
                out[OFF_B + ((size_t)t * BB + b0 + bb) * BEL + j] = nb;
            }
        }
        __syncthreads();

        // ===== PhD: hp/hq partials, 400 threads = 200 col-pairs x 2 k-halves =====
        if (tid < 400) {
            const int p = tid % 200;
            const int half = tid / 200;
            const ulonglong2* __restrict__ wp = (const ulonglong2*)g_Wh2 + p * 2;
            u64 accA[8], accB[8];
#pragma unroll
            for (int bb = 0; bb < 8; bb++) { accA[bb] = 0ULL; accB[bb] = 0ULL; }
            const int kb = half * 25;
            ulonglong2 w0a = wp[(kb) * 400],     w0b = wp[(kb) * 400 + 1];
            ulonglong2 w1a = wp[(kb + 1) * 400], w1b = wp[(kb + 1) * 400 + 1];
#pragma unroll 2
            for (int kk = 0; kk < 25; kk++) {
                int k4 = kb + kk;
                ulonglong2 wa = w0a, wb = w0b;
                w0a = w1a; w0b = w1b;
                if (kk + 2 < 25) {
                    w1a = wp[(k4 + 2) * 400];
                    w1b = wp[(k4 + 2) * 400 + 1];
                }
#pragma unroll
                for (int bb = 0; bb < 8; bb++) {
                    ulonglong2 h = *(const ulonglong2*)&bel[bb * 200 + k4 * 4];
                    ffma2(accA[bb], h.x, wa.x); ffma2(accA[bb], h.y, wa.y);
                    ffma2(accB[bb], h.x, wb.x); ffma2(accB[bb], h.y, wb.y);
                }
            }
#pragma unroll
            for (int bb = 0; bb < 8; bb++) {
                gig[half * 3200 + bb * 400 + 2 * p]     = hsum2(accA[bb]);
                gig[half * 3200 + bb * 400 + 2 * p + 1] = hsum2(accB[bb]);
            }
        }
        __syncthreads();

        // ===== reduce partials -> hp/hq with relu =====
        if (tid < 400) {
#pragma unroll
            for (int bb = 0; bb < 8; bb++) {
                float v = gig[bb * 400 + tid] + gig[3200 + bb * 400 + tid];
                if (tid < 200) hp[bb * 200 + tid] = fmaxf(v + r_bbp, 0.f);
                else hq[bb * 200 + tid - 200] = fmaxf(v + obs[bb * 200 + tid - 200], 0.f);
            }
        }
        __syncthreads();

        // ===== PhE: head projections, k-split 5 =====
        if (tid < 600) {
            const int g = tid % 120, q = tid / 120;
            const float* src = (g < 60) ? hp : hq;
            u64 acc[8];
#pragma unroll
            for (int bb = 0; bb < 8; bb++) acc[bb] = 0ULL;
#pragma unroll
            for (int kk = 0; kk < 10; kk++) {
                int k4 = q * 10 + kk;
                ulonglong2 w = __ldg((const ulonglong2*)&g_Wo4[(k4 * 120 + g) << 2]);
#pragma unroll
                for (int bb = 0; bb < 8; bb++) {
                    ulonglong2 h = *(const ulonglong2*)&src[bb * 200 + k4 * 4];
                    ffma2(acc[bb], h.x, w.x);
                    ffma2(acc[bb], h.y, w.y);
                }
            }
#pragma unroll
            for (int bb = 0; bb < 8; bb++)
                gig[q * 960 + bb * 120 + g] = hsum2(acc[bb]);
        }
        __syncthreads();

        // ===== PhF: reduce heads, sample, write outputs, next s_sh =====
        if (tid < 240) {
            const int bb = tid / 30, i = tid - bb * 30;
            size_t gidx = ((size_t)t * BB + b0 + bb) * ST + i;
            float np = noise_p[gidx], nq = noise_q[gidx];
            float mp = bias[i], spr = bias[30 + i], mq = bias[60 + i], sqr = bias[90 + i];
#pragma unroll
            for (int q = 0; q < 5; q++) {
                mp  += gig[q * 960 + bb * 120 + i];
                spr += gig[q * 960 + bb * 120 + 30 + i];
                mq  += gig[q * 960 + bb * 120 + 60 + i];
                sqr += gig[q * 960 + bb * 120 + 90 + i];
            }
            float spv = softplusf(spr) + 0.1f;
            float sqv = softplusf(sqr) + 0.1f;
            float po  = fmaf(sqv, nq, mq);
            out[OFF_MP + gidx] = mp;
            out[OFF_SP + gidx] = spv;
            out[OFF_PS + gidx] = fmaf(spv, np, mp);
            out[OFF_MQ + gidx] = mq;
            out[OFF_SQ + gidx] = sqv;
            out[OFF_PO + gidx] = po;
            if (t + 1 < TT)
                s_sh[bb * 40 + i] = po * nonterm[(size_t)(t + 1) * BB + b0 + bb];
        } else if (tid < 304) {
            int idx = tid - 240, bb = idx >> 3, i = idx & 7;
            if (t + 1 < TT)
                s_sh[bb * 40 + 30 + i] = actions[((size_t)(t + 1) * BB + b0 + bb) * ACT + i];
        }
        __syncthreads();
    }
}

// ---------------------------------------------------------------------------
extern "C" void kernel_launch(void* const* d_in, const int* in_sizes, int n_in,
                              void* d_out, int out_size) {
    const float* prev_state   = (const float*)d_in[0];
    const float* actions      = (const float*)d_in[1];
    const float* prev_belief  = (const float*)d_in[2];
    const float* observations = (const float*)d_in[3];
    const float* nonterm      = (const float*)d_in[4];
    const float* noise_p      = (const float*)d_in[5];
    const float* noise_q      = (const float*)d_in[6];
    const float* W_sa = (const float*)d_in[7];  const float* b_sa = (const float*)d_in[8];
    const float* W_ih = (const float*)d_in[9];  const float* b_ih = (const float*)d_in[10];
    const float* W_hh = (const float*)d_in[11]; const float* b_hh = (const float*)d_in[12];
    const float* W_bp = (const float*)d_in[13]; const float* b_bp = (const float*)d_in[14];
    const float* W_sp = (const float*)d_in[15]; const float* b_sp = (const float*)d_in[16];
    const float* W_bq = (const float*)d_in[17]; const float* b_bq = (const float*)d_in[18];
    const float* W_sq = (const float*)d_in[19]; const float* b_sq = (const float*)d_in[20];
    float* out = (float*)d_out;
    (void)in_sizes; (void)n_in; (void)out_size;

    static int done = 0;
    if (!done) {
        cudaFuncSetAttribute(k_scan, cudaFuncAttributeMaxDynamicSharedMemorySize, SCAN_SMEM);
        done = 1;
    }
    k_prep<<<(PREP_N + 255) / 256, 256>>>(W_sa, W_ih, W_hh, W_bp, W_sp, W_bq, W_sq);
    k_obs_gemm<<<(TT * BB) / 64, 640>>>(observations, W_bq, b_bq);
    k_scan<<<BB / 8, 640, SCAN_SMEM>>>(nonterm, prev_state, prev_belief, actions,
                                       noise_p, noise_q, b_sa, b_ih, b_hh,
                                       b_bp, b_sp, b_sq, out);
}